// round 9
// baseline (speedup 1.0000x reference)
#include <cuda_runtime.h>
#include <cuda_fp16.h>
#include <cstdint>

// ---------------------------------------------------------------------------
// Problem constants
// ---------------------------------------------------------------------------
#define NTOK   16384      // B*S
#define DIN    2048
#define DOUT   2048
#define RANK   16
#define NADAPT 8
#define KEXT   (NADAPT*RANK)    // 128
#define KTOT   (DIN + KEXT)     // 2176

// Main GEMM tiling: CTA 256x128, 8 warps (4M x 2N), warp tile 64x64
#define BM 256
#define BN 128
#define BKL 128                 // fp16 per chunk = 256 bytes/row
#define NCH (KTOT / BKL)        // 17
#define A_ST (BM * 256)         // 65536
#define B_ST (BN * 256)         // 32768
#define ST_BYTES (A_ST + B_ST)  // 98304
#define SMEM_BYTES (2 * ST_BYTES)   // 196608 (2 stages)

// prep smem: 2-stage double buffer, 2 x 16KB per stage
#define P_ST_BYTES 16384
#define P_SMEM_BYTES (2 * 2 * P_ST_BYTES)          // 65536

// fp16 K-extended operand buffers
__device__ __half g_xh[(size_t)NTOK * KTOT];
__device__ __half g_wh[(size_t)DOUT * KTOT];

// ---------------------------------------------------------------------------
// Helpers
// ---------------------------------------------------------------------------
__device__ __forceinline__ uint32_t smem_u32(const void* p) {
    uint32_t a;
    asm("{ .reg .u64 t; cvta.to.shared.u64 t, %1; cvt.u32.u64 %0, t; }"
        : "=r"(a) : "l"(p));
    return a;
}

__device__ __forceinline__ void cp_async16(uint32_t dst, const void* src) {
    asm volatile("cp.async.cg.shared.global [%0], [%1], 16;"
                 :: "r"(dst), "l"(src) : "memory");
}

__device__ __forceinline__ void ldsm_x4(uint32_t* r, uint32_t addr) {
    asm volatile("ldmatrix.sync.aligned.m8n8.x4.shared.b16 {%0,%1,%2,%3}, [%4];"
                 : "=r"(r[0]), "=r"(r[1]), "=r"(r[2]), "=r"(r[3]) : "r"(addr));
}

__device__ __forceinline__ void mma_f16_16816(
    float* c, const uint32_t* a, const uint32_t* b)
{
    asm volatile(
        "mma.sync.aligned.m16n8k16.row.col.f32.f16.f16.f32 "
        "{%0,%1,%2,%3}, {%4,%5,%6,%7}, {%8,%9}, {%0,%1,%2,%3};"
        : "+f"(c[0]), "+f"(c[1]), "+f"(c[2]), "+f"(c[3])
        : "r"(a[0]), "r"(a[1]), "r"(a[2]), "r"(a[3]),
          "r"(b[0]), "r"(b[1]));
}

__device__ __forceinline__ uint32_t pack_h2(float x, float y) {
    __half2 h = __float22half2_rn(make_float2(x, y));
    return *reinterpret_cast<uint32_t*>(&h);
}

// ---------------------------------------------------------------------------
// Fused prep kernel.
// Blocks [0, 128): prep_xu — x->fp16 into g_xh; U = x @ A_all^T via mma;
//   ext cols = select(aid)*scale*U.
// Blocks [128, 384): prep_w — W fp32 -> g_wh main cols; lora_b into ext cols.
// ---------------------------------------------------------------------------
__global__ void __launch_bounds__(256, 1) fused_prep_kernel(
    const float* __restrict__ x,
    const int*   __restrict__ mapping,
    const float* __restrict__ W,
    const float* __restrict__ lora_a,
    const float* __restrict__ lora_b,
    const float* __restrict__ scaling)
{
    const int tid  = threadIdx.x;
    const int lane = tid & 31;

    if (blockIdx.x >= NTOK / 128) {
        // ---------------- prep_w role ----------------
        const int bw = blockIdx.x - NTOK / 128;
        const int o = bw * 8 + (tid >> 5);
        const float* wr = W + (size_t)o * DIN;
        __half* orow = g_wh + (size_t)o * KTOT;

        for (int d0 = lane * 4; d0 < DIN; d0 += 128) {
            float4 wv = *(const float4*)(wr + d0);
            uint2 ov = make_uint2(pack_h2(wv.x, wv.y), pack_h2(wv.z, wv.w));
            *(uint2*)(orow + d0) = ov;
        }
        int e0 = lane * 4;
        int a = e0 >> 4;
        int r0 = e0 & 15;
        float4 lb = *(const float4*)(lora_b + ((size_t)a * DOUT + o) * RANK + r0);
        uint2 ov = make_uint2(pack_h2(lb.x, lb.y), pack_h2(lb.z, lb.w));
        *(uint2*)(orow + DIN + e0) = ov;
        return;
    }

    // ---------------- prep_xu role ----------------
    extern __shared__ char psmem[];
    const uint32_t sb = smem_u32(psmem);
    const int wid  = tid >> 5;
    const int gid  = lane >> 2;
    const int tig  = lane & 3;
    const int warpM = wid >> 2;     // 0..1 -> 64 token-rows
    const int warpN = wid & 3;      // 0..3 -> 32 U-cols
    const int tBase = blockIdx.x * 128;
    const uint32_t lane7 = lane & 7;

    const int lrow = tid >> 3;      // 0..31
    const int lseg = tid & 7;       // 0..7
    const uint32_t sw_off = (uint32_t)(lseg ^ (lrow & 7)) * 16;

    float acc[4][4][4];
#pragma unroll
    for (int mi = 0; mi < 4; mi++)
#pragma unroll
        for (int ni = 0; ni < 4; ni++)
#pragma unroll
            for (int q = 0; q < 4; q++) acc[mi][ni][q] = 0.0f;

    auto load_stage = [&](int ch, int s) {
        const uint32_t xbase = sb + s * (2 * P_ST_BYTES);
        const uint32_t abase = xbase + P_ST_BYTES;
        const int k0g = ch * 64;
#pragma unroll
        for (int t = 0; t < 4; t++) {
            int row = lrow + t * 32;
            const float* xp = x + (size_t)(tBase + row) * DIN + k0g + lseg * 8;
            float4 v0 = *(const float4*)(xp);
            float4 v1 = *(const float4*)(xp + 4);
            uint4 h = make_uint4(pack_h2(v0.x, v0.y), pack_h2(v0.z, v0.w),
                                 pack_h2(v1.x, v1.y), pack_h2(v1.z, v1.w));
            *(uint4*)(psmem + (xbase - sb) + row * 128 + sw_off) = h;
            *(uint4*)(g_xh + (size_t)(tBase + row) * KTOT + k0g + lseg * 8) = h;
            const float* ap = lora_a + (size_t)row * DIN + k0g + lseg * 8;
            float4 a0 = *(const float4*)(ap);
            float4 a1 = *(const float4*)(ap + 4);
            uint4 ah = make_uint4(pack_h2(a0.x, a0.y), pack_h2(a0.z, a0.w),
                                  pack_h2(a1.x, a1.y), pack_h2(a1.z, a1.w));
            *(uint4*)(psmem + (abase - sb) + row * 128 + sw_off) = ah;
        }
    };

    const int ra = (lane & 7) + ((lane >> 3) & 1) * 8;
    const int ka = lane >> 4;
    const int rb = (lane & 7) + ((lane >> 4) & 1) * 8;
    const int kb = (lane >> 3) & 1;

    load_stage(0, 0);
    __syncthreads();

    for (int ch = 0; ch < DIN / 64; ch++) {
        const int s = ch & 1;
        if (ch + 1 < DIN / 64) load_stage(ch + 1, s ^ 1);

        const uint32_t aw = sb + s * (2 * P_ST_BYTES) + (warpM * 64) * 128;
        const uint32_t bw = sb + s * (2 * P_ST_BYTES) + P_ST_BYTES + (warpN * 32) * 128;

#pragma unroll
        for (int ks = 0; ks < 4; ks++) {
            uint32_t af[4][4];
#pragma unroll
            for (int mi = 0; mi < 4; mi++) {
                uint32_t addr = aw + (mi * 16 + ra) * 128
                              + (((uint32_t)(ks * 2 + ka) ^ lane7) * 16);
                ldsm_x4(af[mi], addr);
            }
            uint32_t bf[4][2];
#pragma unroll
            for (int nj = 0; nj < 2; nj++) {
                uint32_t t[4];
                uint32_t addr = bw + (nj * 16 + rb) * 128
                              + (((uint32_t)(ks * 2 + kb) ^ lane7) * 16);
                ldsm_x4(t, addr);
                bf[2 * nj][0] = t[0]; bf[2 * nj][1] = t[1];
                bf[2 * nj + 1][0] = t[2]; bf[2 * nj + 1][1] = t[3];
            }
#pragma unroll
            for (int mi = 0; mi < 4; mi++)
#pragma unroll
                for (int ni = 0; ni < 4; ni++)
                    mma_f16_16816(acc[mi][ni], af[mi], bf[ni]);
        }
        __syncthreads();
    }

    // epilogue: select adapter slice, scale, write ext cols
#pragma unroll
    for (int mi = 0; mi < 4; mi++) {
        const int r0 = warpM * 64 + mi * 16 + gid;
        const int r1 = r0 + 8;
        const int aid0 = mapping[tBase + r0];
        const int aid1 = mapping[tBase + r1];
        const float s0 = (aid0 > 0) ? scaling[aid0 - 1] : 0.0f;
        const float s1 = (aid1 > 0) ? scaling[aid1 - 1] : 0.0f;
#pragma unroll
        for (int ni = 0; ni < 4; ni++) {
            const int col = warpN * 32 + ni * 8 + tig * 2;
            const bool sel0 = (aid0 > 0) && ((col >> 4) == aid0 - 1);
            const bool sel1 = (aid1 > 0) && ((col >> 4) == aid1 - 1);
            uint32_t v0 = sel0 ? pack_h2(acc[mi][ni][0] * s0, acc[mi][ni][1] * s0) : 0u;
            uint32_t v1 = sel1 ? pack_h2(acc[mi][ni][2] * s1, acc[mi][ni][3] * s1) : 0u;
            *(uint32_t*)(g_xh + (size_t)(tBase + r0) * KTOT + DIN + col) = v0;
            *(uint32_t*)(g_xh + (size_t)(tBase + r1) * KTOT + DIN + col) = v1;
        }
    }
}

// ---------------------------------------------------------------------------
// Main GEMM: CTA 256x128, 8 warps (4M x 2N), warp tile 64x64.
// BK=128 (256B rows, 2 swizzle atoms), 2-stage double buffer,
// fragment double-buffer (ldsm for ks+1 under mma of ks).
// ---------------------------------------------------------------------------
__global__ void __launch_bounds__(256, 1) gemm_h_kernel(
    const float* __restrict__ bias, float* __restrict__ out)
{
    extern __shared__ char smem[];
    const uint32_t sb = smem_u32(smem);
    const int tid  = threadIdx.x;
    const int wid  = tid >> 5;
    const int lane = tid & 31;
    const int gid  = lane >> 2;
    const int tig  = lane & 3;
    const int warpM = wid & 3;      // 0..3 -> 64 rows each
    const int warpN = wid >> 2;     // 0..1 -> 64 cols each
    const int mBase = blockIdx.y * BM;
    const int oBase = blockIdx.x * BN;
    const uint32_t lane7 = lane & 7;

    float acc[4][8][4];
#pragma unroll
    for (int mi = 0; mi < 4; mi++)
#pragma unroll
        for (int n = 0; n < 8; n++)
#pragma unroll
            for (int q = 0; q < 4; q++) acc[mi][n][q] = 0.0f;

    // staging: 256 threads; A: 256 rows x 16 segs (16 iters), B: 128 x 16 (8)
    const int srow = tid >> 4;      // 0..15
    const int sseg = tid & 15;      // 0..15
    const uint32_t st_off = (uint32_t)(sseg >> 3) * 128
                          + (uint32_t)((sseg & 7) ^ (srow & 7)) * 16;

    auto load_stage = [&](int chunk, int slot) {
        const uint32_t abase = sb + slot * ST_BYTES;
        const uint32_t bbase = abase + A_ST;
        const size_t koff = (size_t)chunk * BKL + sseg * 8;
#pragma unroll
        for (int t = 0; t < 16; t++) {          // A: 256 rows
            int row = srow + t * 16;
            cp_async16(abase + row * 256 + st_off,
                       g_xh + (size_t)(mBase + row) * KTOT + koff);
        }
#pragma unroll
        for (int t = 0; t < 8; t++) {           // B: 128 rows
            int row = srow + t * 16;
            cp_async16(bbase + row * 256 + st_off,
                       g_wh + (size_t)(oBase + row) * KTOT + koff);
        }
        asm volatile("cp.async.commit_group;" ::: "memory");
    };

    load_stage(0, 0);

    // ldmatrix lane addressing (constant per thread)
    const int ra = (lane & 7) + ((lane >> 3) & 1) * 8;
    const int ka = lane >> 4;
    const int rb = (lane & 7) + ((lane >> 4) & 1) * 8;
    const int kb = (lane >> 3) & 1;

    uint32_t af[2][4][4];
    uint32_t bf[2][8][2];

    for (int i = 0; i < NCH; i++) {
        asm volatile("cp.async.wait_group 0;" ::: "memory");
        __syncthreads();

        if (i + 1 < NCH) load_stage(i + 1, (i + 1) & 1);

        const int slot = i & 1;
        const uint32_t aw = sb + slot * ST_BYTES + (warpM * 64) * 256;
        const uint32_t bw = sb + slot * ST_BYTES + A_ST + (warpN * 64) * 256;

        auto ldsm_set = [&](int ks, int b) {
            const uint32_t sa = (uint32_t)(ks * 2 + ka);
            const uint32_t sb2 = (uint32_t)(ks * 2 + kb);
            const uint32_t aoff = (sa >> 3) * 128 + (((sa & 7) ^ lane7) * 16);
            const uint32_t boff = (sb2 >> 3) * 128 + (((sb2 & 7) ^ lane7) * 16);
#pragma unroll
            for (int mi = 0; mi < 4; mi++)
                ldsm_x4(af[b][mi], aw + (mi * 16 + ra) * 256 + aoff);
#pragma unroll
            for (int nj = 0; nj < 4; nj++) {
                uint32_t t[4];
                ldsm_x4(t, bw + (nj * 16 + rb) * 256 + boff);
                bf[b][2 * nj][0] = t[0]; bf[b][2 * nj][1] = t[1];
                bf[b][2 * nj + 1][0] = t[2]; bf[b][2 * nj + 1][1] = t[3];
            }
        };
        auto mma_set = [&](int b) {
#pragma unroll
            for (int mi = 0; mi < 4; mi++)
#pragma unroll
                for (int n = 0; n < 8; n++)
                    mma_f16_16816(acc[mi][n], af[b][mi], bf[b][n]);
        };

        ldsm_set(0, 0);
#pragma unroll
        for (int ks = 0; ks < 7; ks++) {
            ldsm_set(ks + 1, (ks + 1) & 1);
            mma_set(ks & 1);
        }
        mma_set(7 & 1);
    }

    // epilogue: bias + store
#pragma unroll
    for (int mi = 0; mi < 4; mi++) {
        const int row = mBase + warpM * 64 + mi * 16 + gid;
#pragma unroll
        for (int n = 0; n < 8; n++) {
            const int col = oBase + warpN * 64 + n * 8 + tig * 2;
            float2 b2 = *(const float2*)(bias + col);
            float2 o0, o1;
            o0.x = acc[mi][n][0] + b2.x;
            o0.y = acc[mi][n][1] + b2.y;
            o1.x = acc[mi][n][2] + b2.x;
            o1.y = acc[mi][n][3] + b2.y;
            *(float2*)(out + (size_t)row * DOUT + col) = o0;
            *(float2*)(out + (size_t)(row + 8) * DOUT + col) = o1;
        }
    }
}

// ---------------------------------------------------------------------------
// Inputs: x, lora_mapping, weight, bias, lora_a, lora_b, scaling
// ---------------------------------------------------------------------------
extern "C" void kernel_launch(void* const* d_in, const int* in_sizes, int n_in,
                              void* d_out, int out_size)
{
    const float* x       = (const float*)d_in[0];
    const int*   mapping = (const int*)  d_in[1];
    const float* weight  = (const float*)d_in[2];
    const float* bias    = (const float*)d_in[3];
    const float* lora_a  = (const float*)d_in[4];
    const float* lora_b  = (const float*)d_in[5];
    const float* scaling = (const float*)d_in[6];
    float*       out     = (float*)d_out;

    cudaFuncSetAttribute(gemm_h_kernel,
                         cudaFuncAttributeMaxDynamicSharedMemorySize, SMEM_BYTES);
    cudaFuncSetAttribute(fused_prep_kernel,
                         cudaFuncAttributeMaxDynamicSharedMemorySize, P_SMEM_BYTES);

    fused_prep_kernel<<<NTOK / 128 + DOUT / 8, 256, P_SMEM_BYTES>>>(
        x, mapping, weight, lora_a, lora_b, scaling);

    dim3 grid(DOUT / BN, NTOK / BM);
    gemm_h_kernel<<<grid, 256, SMEM_BYTES>>>(bias, out);
}

// round 10
// speedup vs baseline: 1.0192x; 1.0192x over previous
#include <cuda_runtime.h>
#include <cuda_fp16.h>
#include <cstdint>

// ---------------------------------------------------------------------------
// Problem constants
// ---------------------------------------------------------------------------
#define NTOK   16384      // B*S
#define DIN    2048
#define DOUT   2048
#define RANK   16
#define NADAPT 8
#define KEXT   (NADAPT*RANK)    // 128
#define KTOT   (DIN + KEXT)     // 2176

// Main GEMM tiling: CTA 128x128, 8 warps (2M x 4N), warp tile 64x32
#define BM 128
#define BN 128
#define BK 64                   // fp16 per chunk = 128 bytes/row
#define NCH (KTOT / BK)         // 34
#define STAGES 3
#define A_ST (BM * 128)         // 16384
#define B_ST (BN * 128)         // 16384
#define ST_BYTES (A_ST + B_ST)  // 32768
#define SMEM_BYTES (STAGES * ST_BYTES)   // 98304 -> 2 CTAs/SM

// prep_xu smem: 2-stage double buffer; per stage: x 8KB + A 16KB
#define PX_ST 8192
#define PA_ST 16384
#define P_ST  (PX_ST + PA_ST)              // 24576
#define P_SMEM_BYTES (2 * P_ST)            // 49152

// fp16 K-extended operand buffers
__device__ __half g_xh[(size_t)NTOK * KTOT];
__device__ __half g_wh[(size_t)DOUT * KTOT];

// ---------------------------------------------------------------------------
// Helpers
// ---------------------------------------------------------------------------
__device__ __forceinline__ uint32_t smem_u32(const void* p) {
    uint32_t a;
    asm("{ .reg .u64 t; cvta.to.shared.u64 t, %1; cvt.u32.u64 %0, t; }"
        : "=r"(a) : "l"(p));
    return a;
}

__device__ __forceinline__ void cp_async16(uint32_t dst, const void* src) {
    asm volatile("cp.async.cg.shared.global [%0], [%1], 16;"
                 :: "r"(dst), "l"(src) : "memory");
}

__device__ __forceinline__ void ldsm_x4(uint32_t* r, uint32_t addr) {
    asm volatile("ldmatrix.sync.aligned.m8n8.x4.shared.b16 {%0,%1,%2,%3}, [%4];"
                 : "=r"(r[0]), "=r"(r[1]), "=r"(r[2]), "=r"(r[3]) : "r"(addr));
}

__device__ __forceinline__ void mma_f16_16816(
    float* c, const uint32_t* a, const uint32_t* b)
{
    asm volatile(
        "mma.sync.aligned.m16n8k16.row.col.f32.f16.f16.f32 "
        "{%0,%1,%2,%3}, {%4,%5,%6,%7}, {%8,%9}, {%0,%1,%2,%3};"
        : "+f"(c[0]), "+f"(c[1]), "+f"(c[2]), "+f"(c[3])
        : "r"(a[0]), "r"(a[1]), "r"(a[2]), "r"(a[3]),
          "r"(b[0]), "r"(b[1]));
}

__device__ __forceinline__ uint32_t pack_h2(float x, float y) {
    __half2 h = __float22half2_rn(make_float2(x, y));
    return *reinterpret_cast<uint32_t*>(&h);
}

// ---------------------------------------------------------------------------
// Fused prep kernel.
// Blocks [0, 256): prep_xu on 64-token tiles — x->fp16 into g_xh;
//   U = x @ A_all^T via ldmatrix+mma; ext cols = select(aid)*scale*U.
// Blocks [256, 512): prep_w — W fp32 -> g_wh main cols; lora_b into ext cols.
// ---------------------------------------------------------------------------
#define NXB (NTOK / 64)    // 256 xu blocks

__global__ void __launch_bounds__(256, 1) fused_prep_kernel(
    const float* __restrict__ x,
    const int*   __restrict__ mapping,
    const float* __restrict__ W,
    const float* __restrict__ lora_a,
    const float* __restrict__ lora_b,
    const float* __restrict__ scaling)
{
    const int tid  = threadIdx.x;
    const int lane = tid & 31;

    if (blockIdx.x >= NXB) {
        // ---------------- prep_w role ----------------
        const int bw = blockIdx.x - NXB;
        const int o = bw * 8 + (tid >> 5);
        const float* wr = W + (size_t)o * DIN;
        __half* orow = g_wh + (size_t)o * KTOT;

        for (int d0 = lane * 4; d0 < DIN; d0 += 128) {
            float4 wv = *(const float4*)(wr + d0);
            uint2 ov = make_uint2(pack_h2(wv.x, wv.y), pack_h2(wv.z, wv.w));
            *(uint2*)(orow + d0) = ov;
        }
        int e0 = lane * 4;
        int a = e0 >> 4;
        int r0 = e0 & 15;
        float4 lb = *(const float4*)(lora_b + ((size_t)a * DOUT + o) * RANK + r0);
        uint2 ov = make_uint2(pack_h2(lb.x, lb.y), pack_h2(lb.z, lb.w));
        *(uint2*)(orow + DIN + e0) = ov;
        return;
    }

    // ---------------- prep_xu role: 64 tokens per block ----------------
    extern __shared__ char psmem[];
    const uint32_t sb = smem_u32(psmem);
    const int wid  = tid >> 5;
    const int gid  = lane >> 2;
    const int tig  = lane & 3;
    const int warpM = wid >> 2;     // 0..1 -> 32 token-rows
    const int warpN = wid & 3;      // 0..3 -> 32 U-cols
    const int tBase = blockIdx.x * 64;
    const uint32_t lane7 = lane & 7;

    const int lrow = tid >> 3;      // 0..31
    const int lseg = tid & 7;       // 0..7
    const uint32_t sw_off = (uint32_t)(lseg ^ (lrow & 7)) * 16;

    float acc[2][4][4];
#pragma unroll
    for (int mi = 0; mi < 2; mi++)
#pragma unroll
        for (int ni = 0; ni < 4; ni++)
#pragma unroll
            for (int q = 0; q < 4; q++) acc[mi][ni][q] = 0.0f;

    auto load_stage = [&](int ch, int s) {
        const uint32_t xbase = sb + s * P_ST;
        const uint32_t abase = xbase + PX_ST;
        const int k0g = ch * 64;
        // x: 64 rows x 8 segs = 512 uint4 -> 2 per thread
#pragma unroll
        for (int t = 0; t < 2; t++) {
            int row = lrow + t * 32;
            const float* xp = x + (size_t)(tBase + row) * DIN + k0g + lseg * 8;
            float4 v0 = *(const float4*)(xp);
            float4 v1 = *(const float4*)(xp + 4);
            uint4 h = make_uint4(pack_h2(v0.x, v0.y), pack_h2(v0.z, v0.w),
                                 pack_h2(v1.x, v1.y), pack_h2(v1.z, v1.w));
            *(uint4*)(psmem + (xbase - sb) + row * 128 + sw_off) = h;
            *(uint4*)(g_xh + (size_t)(tBase + row) * KTOT + k0g + lseg * 8) = h;
        }
        // A: 128 rows x 8 segs = 1024 uint4 -> 4 per thread
#pragma unroll
        for (int t = 0; t < 4; t++) {
            int row = lrow + t * 32;
            const float* ap = lora_a + (size_t)row * DIN + k0g + lseg * 8;
            float4 a0 = *(const float4*)(ap);
            float4 a1 = *(const float4*)(ap + 4);
            uint4 ah = make_uint4(pack_h2(a0.x, a0.y), pack_h2(a0.z, a0.w),
                                  pack_h2(a1.x, a1.y), pack_h2(a1.z, a1.w));
            *(uint4*)(psmem + (abase - sb) + row * 128 + sw_off) = ah;
        }
    };

    const int ra = (lane & 7) + ((lane >> 3) & 1) * 8;
    const int ka = lane >> 4;
    const int rb = (lane & 7) + ((lane >> 4) & 1) * 8;
    const int kb = (lane >> 3) & 1;

    load_stage(0, 0);
    __syncthreads();

    for (int ch = 0; ch < DIN / 64; ch++) {
        const int s = ch & 1;
        if (ch + 1 < DIN / 64) load_stage(ch + 1, s ^ 1);

        const uint32_t aw = sb + s * P_ST + (warpM * 32) * 128;
        const uint32_t bw = sb + s * P_ST + PX_ST + (warpN * 32) * 128;

#pragma unroll
        for (int ks = 0; ks < 4; ks++) {
            uint32_t af[2][4];
#pragma unroll
            for (int mi = 0; mi < 2; mi++) {
                uint32_t addr = aw + (mi * 16 + ra) * 128
                              + (((uint32_t)(ks * 2 + ka) ^ lane7) * 16);
                ldsm_x4(af[mi], addr);
            }
            uint32_t bf[4][2];
#pragma unroll
            for (int nj = 0; nj < 2; nj++) {
                uint32_t t[4];
                uint32_t addr = bw + (nj * 16 + rb) * 128
                              + (((uint32_t)(ks * 2 + kb) ^ lane7) * 16);
                ldsm_x4(t, addr);
                bf[2 * nj][0] = t[0]; bf[2 * nj][1] = t[1];
                bf[2 * nj + 1][0] = t[2]; bf[2 * nj + 1][1] = t[3];
            }
#pragma unroll
            for (int mi = 0; mi < 2; mi++)
#pragma unroll
                for (int ni = 0; ni < 4; ni++)
                    mma_f16_16816(acc[mi][ni], af[mi], bf[ni]);
        }
        __syncthreads();
    }

    // epilogue: select adapter slice, scale, write ext cols
#pragma unroll
    for (int mi = 0; mi < 2; mi++) {
        const int r0 = warpM * 32 + mi * 16 + gid;
        const int r1 = r0 + 8;
        const int aid0 = mapping[tBase + r0];
        const int aid1 = mapping[tBase + r1];
        const float s0 = (aid0 > 0) ? scaling[aid0 - 1] : 0.0f;
        const float s1 = (aid1 > 0) ? scaling[aid1 - 1] : 0.0f;
#pragma unroll
        for (int ni = 0; ni < 4; ni++) {
            const int col = warpN * 32 + ni * 8 + tig * 2;
            const bool sel0 = (aid0 > 0) && ((col >> 4) == aid0 - 1);
            const bool sel1 = (aid1 > 0) && ((col >> 4) == aid1 - 1);
            uint32_t v0 = sel0 ? pack_h2(acc[mi][ni][0] * s0, acc[mi][ni][1] * s0) : 0u;
            uint32_t v1 = sel1 ? pack_h2(acc[mi][ni][2] * s1, acc[mi][ni][3] * s1) : 0u;
            *(uint32_t*)(g_xh + (size_t)(tBase + r0) * KTOT + DIN + col) = v0;
            *(uint32_t*)(g_xh + (size_t)(tBase + r1) * KTOT + DIN + col) = v1;
        }
    }
}

// ---------------------------------------------------------------------------
// Main GEMM: CTA 128x128, 8 warps (2M x 4N), warp tile 64x32.
// BK=64 (128B rows), 3-stage cp.async pipeline, 96KB smem -> 2 CTAs/SM.
// ---------------------------------------------------------------------------
__global__ void __launch_bounds__(256, 2) gemm_h_kernel(
    const float* __restrict__ bias, float* __restrict__ out)
{
    extern __shared__ char smem[];
    const uint32_t sb = smem_u32(smem);
    const int tid  = threadIdx.x;
    const int wid  = tid >> 5;
    const int lane = tid & 31;
    const int gid  = lane >> 2;
    const int tig  = lane & 3;
    const int warpM = wid >> 2;     // 0..1 -> 64 rows each
    const int warpN = wid & 3;      // 0..3 -> 32 cols each
    const int mBase = blockIdx.y * BM;
    const int oBase = blockIdx.x * BN;
    const uint32_t lane7 = lane & 7;

    float acc[4][4][4];
#pragma unroll
    for (int mi = 0; mi < 4; mi++)
#pragma unroll
        for (int n = 0; n < 4; n++)
#pragma unroll
            for (int q = 0; q < 4; q++) acc[mi][n][q] = 0.0f;

    // staging: 256 threads; A: 128 rows x 8 segs = 1024 -> 4 iters; B same
    const int lrow = tid >> 3;      // 0..31
    const int lseg = tid & 7;       // 0..7
    const uint32_t st_off = (uint32_t)(lseg ^ (lrow & 7)) * 16;

    auto load_stage = [&](int chunk, int slot) {
        const uint32_t abase = sb + slot * ST_BYTES;
        const uint32_t bbase = abase + A_ST;
        const size_t koff = (size_t)chunk * BK + lseg * 8;
#pragma unroll
        for (int t = 0; t < 4; t++) {
            int row = lrow + t * 32;
            cp_async16(abase + row * 128 + st_off,
                       g_xh + (size_t)(mBase + row) * KTOT + koff);
            cp_async16(bbase + row * 128 + st_off,
                       g_wh + (size_t)(oBase + row) * KTOT + koff);
        }
        asm volatile("cp.async.commit_group;" ::: "memory");
    };

#pragma unroll
    for (int s = 0; s < STAGES - 1; s++) load_stage(s, s);

    // ldmatrix lane addressing (constant per thread)
    const int ra = (lane & 7) + ((lane >> 3) & 1) * 8;
    const int ka = lane >> 4;
    const int rb = (lane & 7) + ((lane >> 4) & 1) * 8;
    const int kb = (lane >> 3) & 1;

    for (int i = 0; i < NCH; i++) {
        asm volatile("cp.async.wait_group %0;" :: "n"(STAGES - 2) : "memory");
        __syncthreads();

        if (i + STAGES - 1 < NCH)
            load_stage(i + STAGES - 1, (i + STAGES - 1) % STAGES);

        const int slot = i % STAGES;
        const uint32_t aw = sb + slot * ST_BYTES + (warpM * 64) * 128;
        const uint32_t bw = sb + slot * ST_BYTES + A_ST + (warpN * 32) * 128;

#pragma unroll
        for (int ks = 0; ks < 4; ks++) {
            uint32_t af[4][4];
#pragma unroll
            for (int mi = 0; mi < 4; mi++) {
                uint32_t addr = aw + (mi * 16 + ra) * 128
                              + (((uint32_t)(ks * 2 + ka) ^ lane7) * 16);
                ldsm_x4(af[mi], addr);
            }
            uint32_t bf[4][2];
#pragma unroll
            for (int nj = 0; nj < 2; nj++) {
                uint32_t t[4];
                uint32_t addr = bw + (nj * 16 + rb) * 128
                              + (((uint32_t)(ks * 2 + kb) ^ lane7) * 16);
                ldsm_x4(t, addr);
                bf[2 * nj][0] = t[0]; bf[2 * nj][1] = t[1];
                bf[2 * nj + 1][0] = t[2]; bf[2 * nj + 1][1] = t[3];
            }
#pragma unroll
            for (int mi = 0; mi < 4; mi++)
#pragma unroll
                for (int n = 0; n < 4; n++)
                    mma_f16_16816(acc[mi][n], af[mi], bf[n]);
        }
    }

    // epilogue: bias + store
#pragma unroll
    for (int mi = 0; mi < 4; mi++) {
        const int row = mBase + warpM * 64 + mi * 16 + gid;
#pragma unroll
        for (int n = 0; n < 4; n++) {
            const int col = oBase + warpN * 32 + n * 8 + tig * 2;
            float2 b2 = *(const float2*)(bias + col);
            float2 o0, o1;
            o0.x = acc[mi][n][0] + b2.x;
            o0.y = acc[mi][n][1] + b2.y;
            o1.x = acc[mi][n][2] + b2.x;
            o1.y = acc[mi][n][3] + b2.y;
            *(float2*)(out + (size_t)row * DOUT + col) = o0;
            *(float2*)(out + (size_t)(row + 8) * DOUT + col) = o1;
        }
    }
}

// ---------------------------------------------------------------------------
// Inputs: x, lora_mapping, weight, bias, lora_a, lora_b, scaling
// ---------------------------------------------------------------------------
extern "C" void kernel_launch(void* const* d_in, const int* in_sizes, int n_in,
                              void* d_out, int out_size)
{
    const float* x       = (const float*)d_in[0];
    const int*   mapping = (const int*)  d_in[1];
    const float* weight  = (const float*)d_in[2];
    const float* bias    = (const float*)d_in[3];
    const float* lora_a  = (const float*)d_in[4];
    const float* lora_b  = (const float*)d_in[5];
    const float* scaling = (const float*)d_in[6];
    float*       out     = (float*)d_out;

    cudaFuncSetAttribute(gemm_h_kernel,
                         cudaFuncAttributeMaxDynamicSharedMemorySize, SMEM_BYTES);
    cudaFuncSetAttribute(fused_prep_kernel,
                         cudaFuncAttributeMaxDynamicSharedMemorySize, P_SMEM_BYTES);

    fused_prep_kernel<<<NXB + DOUT / 8, 256, P_SMEM_BYTES>>>(
        x, mapping, weight, lora_a, lora_b, scaling);

    dim3 grid(DOUT / BN, NTOK / BM);
    gemm_h_kernel<<<grid, 256, SMEM_BYTES>>>(bias, out);
}

// round 11
// speedup vs baseline: 1.0362x; 1.0166x over previous
#include <cuda_runtime.h>
#include <cuda_fp16.h>
#include <cstdint>

// ---------------------------------------------------------------------------
// Problem constants
// ---------------------------------------------------------------------------
#define NTOK   16384      // B*S
#define DIN    2048
#define DOUT   2048
#define RANK   16
#define NADAPT 8
#define KEXT   (NADAPT*RANK)    // 128
#define KTOT   (DIN + KEXT)     // 2176

// Main GEMM tiling (R8 config: best measured)
#define BM 256
#define BN 128
#define BKL 128                 // fp16 per chunk = 256 bytes/row
#define NCH (KTOT / BKL)        // 17
#define A_ST (BM * 256)         // 65536
#define B_ST (BN * 256)         // 32768
#define ST_BYTES (A_ST + B_ST)  // 98304
#define SMEM_BYTES (2 * ST_BYTES)   // 196608 (2 stages)

// prep_xu smem: 2-stage double buffer; per stage: x 8KB + A 16KB
#define PX_ST 8192
#define PA_ST 16384
#define P_ST  (PX_ST + PA_ST)              // 24576
#define P_SMEM_BYTES (2 * P_ST)            // 49152
#define NXB (NTOK / 64)                    // 256 xu blocks

// fp16 buffers
__device__ __half g_xh[(size_t)NTOK * KTOT];
__device__ __half g_wh[(size_t)DOUT * KTOT];
__device__ __half g_ah[(size_t)NADAPT * RANK * DIN];   // [128, 2048]

// ---------------------------------------------------------------------------
// Helpers
// ---------------------------------------------------------------------------
__device__ __forceinline__ uint32_t smem_u32(const void* p) {
    uint32_t a;
    asm("{ .reg .u64 t; cvta.to.shared.u64 t, %1; cvt.u32.u64 %0, t; }"
        : "=r"(a) : "l"(p));
    return a;
}

__device__ __forceinline__ void cp_async16(uint32_t dst, const void* src) {
    asm volatile("cp.async.cg.shared.global [%0], [%1], 16;"
                 :: "r"(dst), "l"(src) : "memory");
}

__device__ __forceinline__ void ldsm_x4(uint32_t* r, uint32_t addr) {
    asm volatile("ldmatrix.sync.aligned.m8n8.x4.shared.b16 {%0,%1,%2,%3}, [%4];"
                 : "=r"(r[0]), "=r"(r[1]), "=r"(r[2]), "=r"(r[3]) : "r"(addr));
}

__device__ __forceinline__ void mma_f16_16816(
    float* c, const uint32_t* a, const uint32_t* b)
{
    asm volatile(
        "mma.sync.aligned.m16n8k16.row.col.f32.f16.f16.f32 "
        "{%0,%1,%2,%3}, {%4,%5,%6,%7}, {%8,%9}, {%0,%1,%2,%3};"
        : "+f"(c[0]), "+f"(c[1]), "+f"(c[2]), "+f"(c[3])
        : "r"(a[0]), "r"(a[1]), "r"(a[2]), "r"(a[3]),
          "r"(b[0]), "r"(b[1]));
}

__device__ __forceinline__ uint32_t pack_h2(float x, float y) {
    __half2 h = __float22half2_rn(make_float2(x, y));
    return *reinterpret_cast<uint32_t*>(&h);
}

// ---------------------------------------------------------------------------
// Kernel 1: prep_wa — 256 blocks x 256 threads.
//   Each block: 8 W rows -> g_wh (+ lora_b ext cols), and 1/256 of lora_a
//   -> g_ah (fp16).
// ---------------------------------------------------------------------------
__global__ void __launch_bounds__(256) prep_wa_kernel(
    const float* __restrict__ W,
    const float* __restrict__ lora_a,
    const float* __restrict__ lora_b)
{
    const int tid  = threadIdx.x;
    const int lane = tid & 31;
    const int o = blockIdx.x * 8 + (tid >> 5);

    const float* wr = W + (size_t)o * DIN;
    __half* orow = g_wh + (size_t)o * KTOT;

    for (int d0 = lane * 4; d0 < DIN; d0 += 128) {
        float4 wv = *(const float4*)(wr + d0);
        uint2 ov = make_uint2(pack_h2(wv.x, wv.y), pack_h2(wv.z, wv.w));
        *(uint2*)(orow + d0) = ov;
    }
    {
        int e0 = lane * 4;
        int a = e0 >> 4;
        int r0 = e0 & 15;
        float4 lb = *(const float4*)(lora_b + ((size_t)a * DOUT + o) * RANK + r0);
        uint2 ov = make_uint2(pack_h2(lb.x, lb.y), pack_h2(lb.z, lb.w));
        *(uint2*)(orow + DIN + e0) = ov;
    }
    // lora_a conversion: 262144 floats / 256 blocks / 256 threads = 4 each
    {
        size_t i = ((size_t)blockIdx.x * 256 + tid) * 4;
        float4 av = *(const float4*)(lora_a + i);
        uint2 ov = make_uint2(pack_h2(av.x, av.y), pack_h2(av.z, av.w));
        *(uint2*)(g_ah + i) = ov;
    }
}

// ---------------------------------------------------------------------------
// Kernel 2: prep_xu — 256 blocks, 64-token tiles. x->fp16 into g_xh;
//   U = x @ A_all^T via ldmatrix+mma (A from fp16 g_ah);
//   ext cols = select(aid)*scale*U.
// ---------------------------------------------------------------------------
__global__ void __launch_bounds__(256, 1) prep_xu_kernel(
    const float* __restrict__ x,
    const int*   __restrict__ mapping,
    const float* __restrict__ scaling)
{
    extern __shared__ char psmem[];
    const uint32_t sb = smem_u32(psmem);
    const int tid  = threadIdx.x;
    const int lane = tid & 31;
    const int wid  = tid >> 5;
    const int gid  = lane >> 2;
    const int tig  = lane & 3;
    const int warpM = wid >> 2;     // 0..1 -> 32 token-rows
    const int warpN = wid & 3;      // 0..3 -> 32 U-cols
    const int tBase = blockIdx.x * 64;
    const uint32_t lane7 = lane & 7;

    const int lrow = tid >> 3;      // 0..31
    const int lseg = tid & 7;       // 0..7
    const uint32_t sw_off = (uint32_t)(lseg ^ (lrow & 7)) * 16;

    float acc[2][4][4];
#pragma unroll
    for (int mi = 0; mi < 2; mi++)
#pragma unroll
        for (int ni = 0; ni < 4; ni++)
#pragma unroll
            for (int q = 0; q < 4; q++) acc[mi][ni][q] = 0.0f;

    auto load_stage = [&](int ch, int s) {
        const uint32_t xbase = sb + s * P_ST;
        const uint32_t abase = xbase + PX_ST;
        const int k0g = ch * 64;
        // x: 64 rows x 8 segs -> 2 per thread (fp32 -> fp16)
#pragma unroll
        for (int t = 0; t < 2; t++) {
            int row = lrow + t * 32;
            const float* xp = x + (size_t)(tBase + row) * DIN + k0g + lseg * 8;
            float4 v0 = *(const float4*)(xp);
            float4 v1 = *(const float4*)(xp + 4);
            uint4 h = make_uint4(pack_h2(v0.x, v0.y), pack_h2(v0.z, v0.w),
                                 pack_h2(v1.x, v1.y), pack_h2(v1.z, v1.w));
            *(uint4*)(psmem + (xbase - sb) + row * 128 + sw_off) = h;
            *(uint4*)(g_xh + (size_t)(tBase + row) * KTOT + k0g + lseg * 8) = h;
        }
        // A: fp16 g_ah, 128 rows x 8 segs -> 4 per thread via cp.async
#pragma unroll
        for (int t = 0; t < 4; t++) {
            int row = lrow + t * 32;
            cp_async16(abase + row * 128 + sw_off,
                       g_ah + (size_t)row * DIN + k0g + lseg * 8);
        }
        asm volatile("cp.async.commit_group;" ::: "memory");
    };

    const int ra = (lane & 7) + ((lane >> 3) & 1) * 8;
    const int ka = lane >> 4;
    const int rb = (lane & 7) + ((lane >> 4) & 1) * 8;
    const int kb = (lane >> 3) & 1;

    load_stage(0, 0);

    for (int ch = 0; ch < DIN / 64; ch++) {
        const int s = ch & 1;
        asm volatile("cp.async.wait_group 0;" ::: "memory");
        __syncthreads();
        if (ch + 1 < DIN / 64) load_stage(ch + 1, s ^ 1);

        const uint32_t aw = sb + s * P_ST + (warpM * 32) * 128;
        const uint32_t bw = sb + s * P_ST + PX_ST + (warpN * 32) * 128;

#pragma unroll
        for (int ks = 0; ks < 4; ks++) {
            uint32_t af[2][4];
#pragma unroll
            for (int mi = 0; mi < 2; mi++) {
                uint32_t addr = aw + (mi * 16 + ra) * 128
                              + (((uint32_t)(ks * 2 + ka) ^ lane7) * 16);
                ldsm_x4(af[mi], addr);
            }
            uint32_t bf[4][2];
#pragma unroll
            for (int nj = 0; nj < 2; nj++) {
                uint32_t t[4];
                uint32_t addr = bw + (nj * 16 + rb) * 128
                              + (((uint32_t)(ks * 2 + kb) ^ lane7) * 16);
                ldsm_x4(t, addr);
                bf[2 * nj][0] = t[0]; bf[2 * nj][1] = t[1];
                bf[2 * nj + 1][0] = t[2]; bf[2 * nj + 1][1] = t[3];
            }
#pragma unroll
            for (int mi = 0; mi < 2; mi++)
#pragma unroll
                for (int ni = 0; ni < 4; ni++)
                    mma_f16_16816(acc[mi][ni], af[mi], bf[ni]);
        }
        __syncthreads();
    }

    // epilogue: select adapter slice, scale, write ext cols
#pragma unroll
    for (int mi = 0; mi < 2; mi++) {
        const int r0 = warpM * 32 + mi * 16 + gid;
        const int r1 = r0 + 8;
        const int aid0 = mapping[tBase + r0];
        const int aid1 = mapping[tBase + r1];
        const float s0 = (aid0 > 0) ? scaling[aid0 - 1] : 0.0f;
        const float s1 = (aid1 > 0) ? scaling[aid1 - 1] : 0.0f;
#pragma unroll
        for (int ni = 0; ni < 4; ni++) {
            const int col = warpN * 32 + ni * 8 + tig * 2;
            const bool sel0 = (aid0 > 0) && ((col >> 4) == aid0 - 1);
            const bool sel1 = (aid1 > 0) && ((col >> 4) == aid1 - 1);
            uint32_t v0 = sel0 ? pack_h2(acc[mi][ni][0] * s0, acc[mi][ni][1] * s0) : 0u;
            uint32_t v1 = sel1 ? pack_h2(acc[mi][ni][2] * s1, acc[mi][ni][3] * s1) : 0u;
            *(uint32_t*)(g_xh + (size_t)(tBase + r0) * KTOT + DIN + col) = v0;
            *(uint32_t*)(g_xh + (size_t)(tBase + r1) * KTOT + DIN + col) = v1;
        }
    }
}

// ---------------------------------------------------------------------------
// Main GEMM (R8 config, best measured): CTA 256x128, 16 warps (4Mx4N),
// warp tile 64x32, BK=128 (256B rows), 2-stage double buffer.
// ---------------------------------------------------------------------------
__global__ void __launch_bounds__(512, 1) gemm_h_kernel(
    const float* __restrict__ bias, float* __restrict__ out)
{
    extern __shared__ char smem[];
    const uint32_t sb = smem_u32(smem);
    const int tid  = threadIdx.x;
    const int wid  = tid >> 5;
    const int lane = tid & 31;
    const int gid  = lane >> 2;
    const int tig  = lane & 3;
    const int warpM = wid & 3;      // 0..3 -> 64 rows each
    const int warpN = wid >> 2;     // 0..3 -> 32 cols each
    const int mBase = blockIdx.y * BM;
    const int oBase = blockIdx.x * BN;
    const uint32_t lane7 = lane & 7;

    float acc[4][4][4];
#pragma unroll
    for (int mi = 0; mi < 4; mi++)
#pragma unroll
        for (int n = 0; n < 4; n++)
#pragma unroll
            for (int q = 0; q < 4; q++) acc[mi][n][q] = 0.0f;

    const int srow = tid >> 4;      // 0..31
    const int sseg = tid & 15;      // 0..15
    const uint32_t st_off = (uint32_t)(sseg >> 3) * 128
                          + (uint32_t)((sseg & 7) ^ (srow & 7)) * 16;

    auto load_stage = [&](int chunk, int slot) {
        const uint32_t abase = sb + slot * ST_BYTES;
        const uint32_t bbase = abase + A_ST;
        const size_t koff = (size_t)chunk * BKL + sseg * 8;
#pragma unroll
        for (int t = 0; t < 8; t++) {           // A: 256 rows
            int row = srow + t * 32;
            cp_async16(abase + row * 256 + st_off,
                       g_xh + (size_t)(mBase + row) * KTOT + koff);
        }
#pragma unroll
        for (int t = 0; t < 4; t++) {           // B: 128 rows
            int row = srow + t * 32;
            cp_async16(bbase + row * 256 + st_off,
                       g_wh + (size_t)(oBase + row) * KTOT + koff);
        }
        asm volatile("cp.async.commit_group;" ::: "memory");
    };

    load_stage(0, 0);

    const int ra = (lane & 7) + ((lane >> 3) & 1) * 8;
    const int ka = lane >> 4;
    const int rb = (lane & 7) + ((lane >> 4) & 1) * 8;
    const int kb = (lane >> 3) & 1;

    for (int i = 0; i < NCH; i++) {
        asm volatile("cp.async.wait_group 0;" ::: "memory");
        __syncthreads();

        if (i + 1 < NCH) load_stage(i + 1, (i + 1) & 1);

        const int slot = i & 1;
        const uint32_t aw = sb + slot * ST_BYTES + (warpM * 64) * 256;
        const uint32_t bw = sb + slot * ST_BYTES + A_ST + (warpN * 32) * 256;

#pragma unroll
        for (int ks = 0; ks < 8; ks++) {
            const uint32_t sa = (uint32_t)(ks * 2 + ka);
            const uint32_t sb2 = (uint32_t)(ks * 2 + kb);
            const uint32_t aoff = (sa >> 3) * 128 + (((sa & 7) ^ lane7) * 16);
            const uint32_t boff = (sb2 >> 3) * 128 + (((sb2 & 7) ^ lane7) * 16);

            uint32_t af[4][4];
#pragma unroll
            for (int mi = 0; mi < 4; mi++)
                ldsm_x4(af[mi], aw + (mi * 16 + ra) * 256 + aoff);

            uint32_t bf[4][2];
#pragma unroll
            for (int nj = 0; nj < 2; nj++) {
                uint32_t t[4];
                ldsm_x4(t, bw + (nj * 16 + rb) * 256 + boff);
                bf[2 * nj][0] = t[0]; bf[2 * nj][1] = t[1];
                bf[2 * nj + 1][0] = t[2]; bf[2 * nj + 1][1] = t[3];
            }
#pragma unroll
            for (int mi = 0; mi < 4; mi++)
#pragma unroll
                for (int n = 0; n < 4; n++)
                    mma_f16_16816(acc[mi][n], af[mi], bf[n]);
        }
    }

    // epilogue: bias + store
#pragma unroll
    for (int mi = 0; mi < 4; mi++) {
        const int row = mBase + warpM * 64 + mi * 16 + gid;
#pragma unroll
        for (int n = 0; n < 4; n++) {
            const int col = oBase + warpN * 32 + n * 8 + tig * 2;
            float2 b2 = *(const float2*)(bias + col);
            float2 o0, o1;
            o0.x = acc[mi][n][0] + b2.x;
            o0.y = acc[mi][n][1] + b2.y;
            o1.x = acc[mi][n][2] + b2.x;
            o1.y = acc[mi][n][3] + b2.y;
            *(float2*)(out + (size_t)row * DOUT + col) = o0;
            *(float2*)(out + (size_t)(row + 8) * DOUT + col) = o1;
        }
    }
}

// ---------------------------------------------------------------------------
// Inputs: x, lora_mapping, weight, bias, lora_a, lora_b, scaling
// ---------------------------------------------------------------------------
extern "C" void kernel_launch(void* const* d_in, const int* in_sizes, int n_in,
                              void* d_out, int out_size)
{
    const float* x       = (const float*)d_in[0];
    const int*   mapping = (const int*)  d_in[1];
    const float* weight  = (const float*)d_in[2];
    const float* bias    = (const float*)d_in[3];
    const float* lora_a  = (const float*)d_in[4];
    const float* lora_b  = (const float*)d_in[5];
    const float* scaling = (const float*)d_in[6];
    float*       out     = (float*)d_out;

    cudaFuncSetAttribute(gemm_h_kernel,
                         cudaFuncAttributeMaxDynamicSharedMemorySize, SMEM_BYTES);
    cudaFuncSetAttribute(prep_xu_kernel,
                         cudaFuncAttributeMaxDynamicSharedMemorySize, P_SMEM_BYTES);

    prep_wa_kernel<<<DOUT / 8, 256>>>(weight, lora_a, lora_b);
    prep_xu_kernel<<<NXB, 256, P_SMEM_BYTES>>>(x, mapping, scaling);

    dim3 grid(DOUT / BN, NTOK / BM);
    gemm_h_kernel<<<grid, 512, SMEM_BYTES>>>(bias, out);
}

// round 12
// speedup vs baseline: 1.0419x; 1.0055x over previous
#include <cuda_runtime.h>
#include <cuda_fp16.h>
#include <cstdint>

// ---------------------------------------------------------------------------
// Problem constants
// ---------------------------------------------------------------------------
#define NTOK   16384      // B*S
#define DIN    2048
#define DOUT   2048
#define RANK   16
#define NADAPT 8
#define KEXT   (NADAPT*RANK)    // 128
#define KTOT   (DIN + KEXT)     // 2176

// Main GEMM tiling (best measured config)
#define BM 256
#define BN 128
#define BKL 128                 // fp16 per chunk = 256 bytes/row
#define NCH (KTOT / BKL)        // 17
#define A_ST (BM * 256)         // 65536
#define B_ST (BN * 256)         // 32768
#define ST_BYTES (A_ST + B_ST)  // 98304
#define SMEM_BYTES (2 * ST_BYTES)   // 196608 (2 stages)

// u_xu smem: 2-stage double buffer; per stage: x 8KB + A 16KB
#define PX_ST 8192
#define PA_ST 16384
#define P_ST  (PX_ST + PA_ST)              // 24576
#define P_SMEM_BYTES (2 * P_ST)            // 49152
#define NXB (NTOK / 64)                    // 256 u_xu blocks

// conv_all block split
#define XCONV_BLOCKS (NTOK / 8)            // 2048 (8 x-rows per block)
#define WCONV_BLOCKS (DOUT / 8)            // 256

// fp16 buffers
__device__ __half g_xh[(size_t)NTOK * KTOT];
__device__ __half g_wh[(size_t)DOUT * KTOT];
__device__ __half g_ah[(size_t)NADAPT * RANK * DIN];   // [128, 2048]

// ---------------------------------------------------------------------------
// Helpers
// ---------------------------------------------------------------------------
__device__ __forceinline__ uint32_t smem_u32(const void* p) {
    uint32_t a;
    asm("{ .reg .u64 t; cvta.to.shared.u64 t, %1; cvt.u32.u64 %0, t; }"
        : "=r"(a) : "l"(p));
    return a;
}

__device__ __forceinline__ void cp_async16(uint32_t dst, const void* src) {
    asm volatile("cp.async.cg.shared.global [%0], [%1], 16;"
                 :: "r"(dst), "l"(src) : "memory");
}

__device__ __forceinline__ void ldsm_x4(uint32_t* r, uint32_t addr) {
    asm volatile("ldmatrix.sync.aligned.m8n8.x4.shared.b16 {%0,%1,%2,%3}, [%4];"
                 : "=r"(r[0]), "=r"(r[1]), "=r"(r[2]), "=r"(r[3]) : "r"(addr));
}

__device__ __forceinline__ void mma_f16_16816(
    float* c, const uint32_t* a, const uint32_t* b)
{
    asm volatile(
        "mma.sync.aligned.m16n8k16.row.col.f32.f16.f16.f32 "
        "{%0,%1,%2,%3}, {%4,%5,%6,%7}, {%8,%9}, {%0,%1,%2,%3};"
        : "+f"(c[0]), "+f"(c[1]), "+f"(c[2]), "+f"(c[3])
        : "r"(a[0]), "r"(a[1]), "r"(a[2]), "r"(a[3]),
          "r"(b[0]), "r"(b[1]));
}

__device__ __forceinline__ uint32_t pack_h2(float x, float y) {
    __half2 h = __float22half2_rn(make_float2(x, y));
    return *reinterpret_cast<uint32_t*>(&h);
}

// ---------------------------------------------------------------------------
// Kernel 1: conv_all — pure-bandwidth fp32->fp16 conversions.
// Blocks [0, 2048): x rows (8 per block) -> g_xh main cols.
// Blocks [2048, 2304): W rows (8 per block) -> g_wh main cols;
//   lora_b -> g_wh ext cols; slice of lora_a -> g_ah.
// ---------------------------------------------------------------------------
__global__ void __launch_bounds__(256) conv_all_kernel(
    const float* __restrict__ x,
    const float* __restrict__ W,
    const float* __restrict__ lora_a,
    const float* __restrict__ lora_b)
{
    const int tid  = threadIdx.x;
    const int lane = tid & 31;
    const int wid  = tid >> 5;

    if (blockIdx.x < XCONV_BLOCKS) {
        const int row = blockIdx.x * 8 + wid;
        const float* xr = x + (size_t)row * DIN;
        __half* orow = g_xh + (size_t)row * KTOT;
#pragma unroll
        for (int i = 0; i < 16; i++) {
            int seg = lane + i * 32;            // 0..511 float4 segments
            float4 v = *(const float4*)(xr + seg * 4);
            uint2 ov = make_uint2(pack_h2(v.x, v.y), pack_h2(v.z, v.w));
            *(uint2*)(orow + seg * 4) = ov;
        }
        return;
    }

    const int bw = blockIdx.x - XCONV_BLOCKS;
    const int o = bw * 8 + wid;
    const float* wr = W + (size_t)o * DIN;
    __half* orow = g_wh + (size_t)o * KTOT;
#pragma unroll
    for (int i = 0; i < 16; i++) {
        int seg = lane + i * 32;
        float4 v = *(const float4*)(wr + seg * 4);
        uint2 ov = make_uint2(pack_h2(v.x, v.y), pack_h2(v.z, v.w));
        *(uint2*)(orow + seg * 4) = ov;
    }
    {   // lora_b ext cols for this W row
        int e0 = lane * 4;
        int a = e0 >> 4;
        int r0 = e0 & 15;
        float4 lb = *(const float4*)(lora_b + ((size_t)a * DOUT + o) * RANK + r0);
        uint2 ov = make_uint2(pack_h2(lb.x, lb.y), pack_h2(lb.z, lb.w));
        *(uint2*)(orow + DIN + e0) = ov;
    }
    {   // lora_a slice: 262144 floats / 256 blocks / 256 threads = 4 each
        size_t i = ((size_t)bw * 256 + tid) * 4;
        float4 av = *(const float4*)(lora_a + i);
        uint2 ov = make_uint2(pack_h2(av.x, av.y), pack_h2(av.z, av.w));
        *(uint2*)(g_ah + i) = ov;
    }
}

// ---------------------------------------------------------------------------
// Kernel 2: u_xu — 256 blocks, 64-token tiles. Reads fp16 g_xh + g_ah via
// cp.async (no conversions); U = x @ A_all^T via ldmatrix+mma;
// ext cols of g_xh = select(aid)*scale*U.
// ---------------------------------------------------------------------------
__global__ void __launch_bounds__(256, 1) u_xu_kernel(
    const int*   __restrict__ mapping,
    const float* __restrict__ scaling)
{
    extern __shared__ char psmem[];
    const uint32_t sb = smem_u32(psmem);
    const int tid  = threadIdx.x;
    const int lane = tid & 31;
    const int wid  = tid >> 5;
    const int gid  = lane >> 2;
    const int tig  = lane & 3;
    const int warpM = wid >> 2;     // 0..1 -> 32 token-rows
    const int warpN = wid & 3;      // 0..3 -> 32 U-cols
    const int tBase = blockIdx.x * 64;
    const uint32_t lane7 = lane & 7;

    const int lrow = tid >> 3;      // 0..31
    const int lseg = tid & 7;       // 0..7
    const uint32_t sw_off = (uint32_t)(lseg ^ (lrow & 7)) * 16;

    float acc[2][4][4];
#pragma unroll
    for (int mi = 0; mi < 2; mi++)
#pragma unroll
        for (int ni = 0; ni < 4; ni++)
#pragma unroll
            for (int q = 0; q < 4; q++) acc[mi][ni][q] = 0.0f;

    auto load_stage = [&](int ch, int s) {
        const uint32_t xbase = sb + s * P_ST;
        const uint32_t abase = xbase + PX_ST;
        const int k0g = ch * 64;
        // x tile (fp16 from g_xh): 64 rows x 8 segs -> 2 cp.async per thread
#pragma unroll
        for (int t = 0; t < 2; t++) {
            int row = lrow + t * 32;
            cp_async16(xbase + row * 128 + sw_off,
                       g_xh + (size_t)(tBase + row) * KTOT + k0g + lseg * 8);
        }
        // A tile (fp16 g_ah): 128 rows x 8 segs -> 4 per thread
#pragma unroll
        for (int t = 0; t < 4; t++) {
            int row = lrow + t * 32;
            cp_async16(abase + row * 128 + sw_off,
                       g_ah + (size_t)row * DIN + k0g + lseg * 8);
        }
        asm volatile("cp.async.commit_group;" ::: "memory");
    };

    const int ra = (lane & 7) + ((lane >> 3) & 1) * 8;
    const int ka = lane >> 4;
    const int rb = (lane & 7) + ((lane >> 4) & 1) * 8;
    const int kb = (lane >> 3) & 1;

    load_stage(0, 0);

    for (int ch = 0; ch < DIN / 64; ch++) {
        const int s = ch & 1;
        asm volatile("cp.async.wait_group 0;" ::: "memory");
        __syncthreads();
        if (ch + 1 < DIN / 64) load_stage(ch + 1, s ^ 1);

        const uint32_t aw = sb + s * P_ST + (warpM * 32) * 128;
        const uint32_t bw = sb + s * P_ST + PX_ST + (warpN * 32) * 128;

#pragma unroll
        for (int ks = 0; ks < 4; ks++) {
            uint32_t af[2][4];
#pragma unroll
            for (int mi = 0; mi < 2; mi++) {
                uint32_t addr = aw + (mi * 16 + ra) * 128
                              + (((uint32_t)(ks * 2 + ka) ^ lane7) * 16);
                ldsm_x4(af[mi], addr);
            }
            uint32_t bf[4][2];
#pragma unroll
            for (int nj = 0; nj < 2; nj++) {
                uint32_t t[4];
                uint32_t addr = bw + (nj * 16 + rb) * 128
                              + (((uint32_t)(ks * 2 + kb) ^ lane7) * 16);
                ldsm_x4(t, addr);
                bf[2 * nj][0] = t[0]; bf[2 * nj][1] = t[1];
                bf[2 * nj + 1][0] = t[2]; bf[2 * nj + 1][1] = t[3];
            }
#pragma unroll
            for (int mi = 0; mi < 2; mi++)
#pragma unroll
                for (int ni = 0; ni < 4; ni++)
                    mma_f16_16816(acc[mi][ni], af[mi], bf[ni]);
        }
        __syncthreads();
    }

    // epilogue: select adapter slice, scale, write ext cols
#pragma unroll
    for (int mi = 0; mi < 2; mi++) {
        const int r0 = warpM * 32 + mi * 16 + gid;
        const int r1 = r0 + 8;
        const int aid0 = mapping[tBase + r0];
        const int aid1 = mapping[tBase + r1];
        const float s0 = (aid0 > 0) ? scaling[aid0 - 1] : 0.0f;
        const float s1 = (aid1 > 0) ? scaling[aid1 - 1] : 0.0f;
#pragma unroll
        for (int ni = 0; ni < 4; ni++) {
            const int col = warpN * 32 + ni * 8 + tig * 2;
            const bool sel0 = (aid0 > 0) && ((col >> 4) == aid0 - 1);
            const bool sel1 = (aid1 > 0) && ((col >> 4) == aid1 - 1);
            uint32_t v0 = sel0 ? pack_h2(acc[mi][ni][0] * s0, acc[mi][ni][1] * s0) : 0u;
            uint32_t v1 = sel1 ? pack_h2(acc[mi][ni][2] * s1, acc[mi][ni][3] * s1) : 0u;
            *(uint32_t*)(g_xh + (size_t)(tBase + r0) * KTOT + DIN + col) = v0;
            *(uint32_t*)(g_xh + (size_t)(tBase + r1) * KTOT + DIN + col) = v1;
        }
    }
}

// ---------------------------------------------------------------------------
// Main GEMM (best measured): CTA 256x128, 16 warps (4Mx4N), warp tile 64x32,
// BK=128 (256B rows), 2-stage double buffer.
// ---------------------------------------------------------------------------
__global__ void __launch_bounds__(512, 1) gemm_h_kernel(
    const float* __restrict__ bias, float* __restrict__ out)
{
    extern __shared__ char smem[];
    const uint32_t sb = smem_u32(smem);
    const int tid  = threadIdx.x;
    const int wid  = tid >> 5;
    const int lane = tid & 31;
    const int gid  = lane >> 2;
    const int tig  = lane & 3;
    const int warpM = wid & 3;      // 0..3 -> 64 rows each
    const int warpN = wid >> 2;     // 0..3 -> 32 cols each
    const int mBase = blockIdx.y * BM;
    const int oBase = blockIdx.x * BN;
    const uint32_t lane7 = lane & 7;

    float acc[4][4][4];
#pragma unroll
    for (int mi = 0; mi < 4; mi++)
#pragma unroll
        for (int n = 0; n < 4; n++)
#pragma unroll
            for (int q = 0; q < 4; q++) acc[mi][n][q] = 0.0f;

    const int srow = tid >> 4;      // 0..31
    const int sseg = tid & 15;      // 0..15
    const uint32_t st_off = (uint32_t)(sseg >> 3) * 128
                          + (uint32_t)((sseg & 7) ^ (srow & 7)) * 16;

    auto load_stage = [&](int chunk, int slot) {
        const uint32_t abase = sb + slot * ST_BYTES;
        const uint32_t bbase = abase + A_ST;
        const size_t koff = (size_t)chunk * BKL + sseg * 8;
#pragma unroll
        for (int t = 0; t < 8; t++) {           // A: 256 rows
            int row = srow + t * 32;
            cp_async16(abase + row * 256 + st_off,
                       g_xh + (size_t)(mBase + row) * KTOT + koff);
        }
#pragma unroll
        for (int t = 0; t < 4; t++) {           // B: 128 rows
            int row = srow + t * 32;
            cp_async16(bbase + row * 256 + st_off,
                       g_wh + (size_t)(oBase + row) * KTOT + koff);
        }
        asm volatile("cp.async.commit_group;" ::: "memory");
    };

    load_stage(0, 0);

    const int ra = (lane & 7) + ((lane >> 3) & 1) * 8;
    const int ka = lane >> 4;
    const int rb = (lane & 7) + ((lane >> 4) & 1) * 8;
    const int kb = (lane >> 3) & 1;

    for (int i = 0; i < NCH; i++) {
        asm volatile("cp.async.wait_group 0;" ::: "memory");
        __syncthreads();

        if (i + 1 < NCH) load_stage(i + 1, (i + 1) & 1);

        const int slot = i & 1;
        const uint32_t aw = sb + slot * ST_BYTES + (warpM * 64) * 256;
        const uint32_t bw = sb + slot * ST_BYTES + A_ST + (warpN * 32) * 256;

#pragma unroll
        for (int ks = 0; ks < 8; ks++) {
            const uint32_t sa = (uint32_t)(ks * 2 + ka);
            const uint32_t sb2 = (uint32_t)(ks * 2 + kb);
            const uint32_t aoff = (sa >> 3) * 128 + (((sa & 7) ^ lane7) * 16);
            const uint32_t boff = (sb2 >> 3) * 128 + (((sb2 & 7) ^ lane7) * 16);

            uint32_t af[4][4];
#pragma unroll
            for (int mi = 0; mi < 4; mi++)
                ldsm_x4(af[mi], aw + (mi * 16 + ra) * 256 + aoff);

            uint32_t bf[4][2];
#pragma unroll
            for (int nj = 0; nj < 2; nj++) {
                uint32_t t[4];
                ldsm_x4(t, bw + (nj * 16 + rb) * 256 + boff);
                bf[2 * nj][0] = t[0]; bf[2 * nj][1] = t[1];
                bf[2 * nj + 1][0] = t[2]; bf[2 * nj + 1][1] = t[3];
            }
#pragma unroll
            for (int mi = 0; mi < 4; mi++)
#pragma unroll
                for (int n = 0; n < 4; n++)
                    mma_f16_16816(acc[mi][n], af[mi], bf[n]);
        }
    }

    // epilogue: bias + store
#pragma unroll
    for (int mi = 0; mi < 4; mi++) {
        const int row = mBase + warpM * 64 + mi * 16 + gid;
#pragma unroll
        for (int n = 0; n < 4; n++) {
            const int col = oBase + warpN * 32 + n * 8 + tig * 2;
            float2 b2 = *(const float2*)(bias + col);
            float2 o0, o1;
            o0.x = acc[mi][n][0] + b2.x;
            o0.y = acc[mi][n][1] + b2.y;
            o1.x = acc[mi][n][2] + b2.x;
            o1.y = acc[mi][n][3] + b2.y;
            *(float2*)(out + (size_t)row * DOUT + col) = o0;
            *(float2*)(out + (size_t)(row + 8) * DOUT + col) = o1;
        }
    }
}

// ---------------------------------------------------------------------------
// Inputs: x, lora_mapping, weight, bias, lora_a, lora_b, scaling
// ---------------------------------------------------------------------------
extern "C" void kernel_launch(void* const* d_in, const int* in_sizes, int n_in,
                              void* d_out, int out_size)
{
    const float* x       = (const float*)d_in[0];
    const int*   mapping = (const int*)  d_in[1];
    const float* weight  = (const float*)d_in[2];
    const float* bias    = (const float*)d_in[3];
    const float* lora_a  = (const float*)d_in[4];
    const float* lora_b  = (const float*)d_in[5];
    const float* scaling = (const float*)d_in[6];
    float*       out     = (float*)d_out;

    cudaFuncSetAttribute(gemm_h_kernel,
                         cudaFuncAttributeMaxDynamicSharedMemorySize, SMEM_BYTES);
    cudaFuncSetAttribute(u_xu_kernel,
                         cudaFuncAttributeMaxDynamicSharedMemorySize, P_SMEM_BYTES);

    conv_all_kernel<<<XCONV_BLOCKS + WCONV_BLOCKS, 256>>>(x, weight, lora_a, lora_b);
    u_xu_kernel<<<NXB, 256, P_SMEM_BYTES>>>(mapping, scaling);

    dim3 grid(DOUT / BN, NTOK / BM);
    gemm_h_kernel<<<grid, 512, SMEM_BYTES>>>(bias, out);
}

// round 14
// speedup vs baseline: 1.0563x; 1.0138x over previous
#include <cuda_runtime.h>
#include <cuda_fp16.h>
#include <cstdint>

// ---------------------------------------------------------------------------
// Problem constants
// ---------------------------------------------------------------------------
#define NTOK   16384      // B*S
#define DIN    2048
#define DOUT   2048
#define RANK   16
#define NADAPT 8
#define KEXT   (NADAPT*RANK)    // 128
#define KTOT   (DIN + KEXT)     // 2176

// Main GEMM tiling (best measured config, unchanged)
#define BM 256
#define BN 128
#define BKL 128                 // fp16 per chunk = 256 bytes/row
#define NCH (KTOT / BKL)        // 17
#define A_ST (BM * 256)         // 65536
#define B_ST (BN * 256)         // 32768
#define ST_BYTES (A_ST + B_ST)  // 98304
#define SMEM_BYTES (2 * ST_BYTES)   // 196608 (2 stages)

// u_xu smem: 3-stage ring; per stage: x 8KB + A 16KB
#define PX_ST 8192
#define PA_ST 16384
#define P_ST  (PX_ST + PA_ST)              // 24576
#define P_STAGES 3
#define P_SMEM_BYTES (P_STAGES * P_ST)     // 73728
#define NXB (NTOK / 64)                    // 256 u_xu blocks
#define PNCH (DIN / 64)                    // 32 chunks

// conv_all block split
#define XCONV_BLOCKS (NTOK / 8)            // 2048 (8 x-rows per block)
#define WCONV_BLOCKS (DOUT / 8)            // 256

// fp16 buffers
__device__ __half g_xh[(size_t)NTOK * KTOT];
__device__ __half g_wh[(size_t)DOUT * KTOT];
__device__ __half g_ah[(size_t)NADAPT * RANK * DIN];   // [128, 2048]

// ---------------------------------------------------------------------------
// Helpers
// ---------------------------------------------------------------------------
__device__ __forceinline__ uint32_t smem_u32(const void* p) {
    uint32_t a;
    asm("{ .reg .u64 t; cvta.to.shared.u64 t, %1; cvt.u32.u64 %0, t; }"
        : "=r"(a) : "l"(p));
    return a;
}

__device__ __forceinline__ void cp_async16(uint32_t dst, const void* src) {
    asm volatile("cp.async.cg.shared.global [%0], [%1], 16;"
                 :: "r"(dst), "l"(src) : "memory");
}

__device__ __forceinline__ void ldsm_x4(uint32_t* r, uint32_t addr) {
    asm volatile("ldmatrix.sync.aligned.m8n8.x4.shared.b16 {%0,%1,%2,%3}, [%4];"
                 : "=r"(r[0]), "=r"(r[1]), "=r"(r[2]), "=r"(r[3]) : "r"(addr));
}

__device__ __forceinline__ void mma_f16_16816(
    float* c, const uint32_t* a, const uint32_t* b)
{
    asm volatile(
        "mma.sync.aligned.m16n8k16.row.col.f32.f16.f16.f32 "
        "{%0,%1,%2,%3}, {%4,%5,%6,%7}, {%8,%9}, {%0,%1,%2,%3};"
        : "+f"(c[0]), "+f"(c[1]), "+f"(c[2]), "+f"(c[3])
        : "r"(a[0]), "r"(a[1]), "r"(a[2]), "r"(a[3]),
          "r"(b[0]), "r"(b[1]));
}

__device__ __forceinline__ uint32_t pack_h2(float x, float y) {
    __half2 h = __float22half2_rn(make_float2(x, y));
    return *reinterpret_cast<uint32_t*>(&h);
}

// ---------------------------------------------------------------------------
// Kernel 1: conv_all — pure-bandwidth fp32->fp16 conversions (at DRAM floor).
// ---------------------------------------------------------------------------
__global__ void __launch_bounds__(256) conv_all_kernel(
    const float* __restrict__ x,
    const float* __restrict__ W,
    const float* __restrict__ lora_a,
    const float* __restrict__ lora_b)
{
    const int tid  = threadIdx.x;
    const int lane = tid & 31;
    const int wid  = tid >> 5;

    if (blockIdx.x < XCONV_BLOCKS) {
        const int row = blockIdx.x * 8 + wid;
        const float* xr = x + (size_t)row * DIN;
        __half* orow = g_xh + (size_t)row * KTOT;
#pragma unroll
        for (int i = 0; i < 16; i++) {
            int seg = lane + i * 32;
            float4 v = *(const float4*)(xr + seg * 4);
            uint2 ov = make_uint2(pack_h2(v.x, v.y), pack_h2(v.z, v.w));
            *(uint2*)(orow + seg * 4) = ov;
        }
        return;
    }

    const int bw = blockIdx.x - XCONV_BLOCKS;
    const int o = bw * 8 + wid;
    const float* wr = W + (size_t)o * DIN;
    __half* orow = g_wh + (size_t)o * KTOT;
#pragma unroll
    for (int i = 0; i < 16; i++) {
        int seg = lane + i * 32;
        float4 v = *(const float4*)(wr + seg * 4);
        uint2 ov = make_uint2(pack_h2(v.x, v.y), pack_h2(v.z, v.w));
        *(uint2*)(orow + seg * 4) = ov;
    }
    {   // lora_b ext cols for this W row
        int e0 = lane * 4;
        int a = e0 >> 4;
        int r0 = e0 & 15;
        float4 lb = *(const float4*)(lora_b + ((size_t)a * DOUT + o) * RANK + r0);
        uint2 ov = make_uint2(pack_h2(lb.x, lb.y), pack_h2(lb.z, lb.w));
        *(uint2*)(orow + DIN + e0) = ov;
    }
    {   // lora_a slice: 4 floats per thread
        size_t i = ((size_t)bw * 256 + tid) * 4;
        float4 av = *(const float4*)(lora_a + i);
        uint2 ov = make_uint2(pack_h2(av.x, av.y), pack_h2(av.z, av.w));
        *(uint2*)(g_ah + i) = ov;
    }
}

// ---------------------------------------------------------------------------
// Kernel 2: u_xu — 256 blocks, 64-token tiles, 3-stage cp.async ring
// (2 chunks in flight; wait_group 0 on the final iteration to drain).
// U = x @ A_all^T via ldmatrix+mma; ext cols of g_xh = select(aid)*scale*U.
// ---------------------------------------------------------------------------
__global__ void __launch_bounds__(256, 3) u_xu_kernel(
    const int*   __restrict__ mapping,
    const float* __restrict__ scaling)
{
    extern __shared__ char psmem[];
    const uint32_t sb = smem_u32(psmem);
    const int tid  = threadIdx.x;
    const int lane = tid & 31;
    const int wid  = tid >> 5;
    const int gid  = lane >> 2;
    const int tig  = lane & 3;
    const int warpM = wid >> 2;     // 0..1 -> 32 token-rows
    const int warpN = wid & 3;      // 0..3 -> 32 U-cols
    const int tBase = blockIdx.x * 64;
    const uint32_t lane7 = lane & 7;

    const int lrow = tid >> 3;      // 0..31
    const int lseg = tid & 7;       // 0..7
    const uint32_t sw_off = (uint32_t)(lseg ^ (lrow & 7)) * 16;

    float acc[2][4][4];
#pragma unroll
    for (int mi = 0; mi < 2; mi++)
#pragma unroll
        for (int ni = 0; ni < 4; ni++)
#pragma unroll
            for (int q = 0; q < 4; q++) acc[mi][ni][q] = 0.0f;

    auto load_stage = [&](int ch) {
        const int s = ch % P_STAGES;
        const uint32_t xbase = sb + s * P_ST;
        const uint32_t abase = xbase + PX_ST;
        const int k0g = ch * 64;
#pragma unroll
        for (int t = 0; t < 2; t++) {
            int row = lrow + t * 32;
            cp_async16(xbase + row * 128 + sw_off,
                       g_xh + (size_t)(tBase + row) * KTOT + k0g + lseg * 8);
        }
#pragma unroll
        for (int t = 0; t < 4; t++) {
            int row = lrow + t * 32;
            cp_async16(abase + row * 128 + sw_off,
                       g_ah + (size_t)row * DIN + k0g + lseg * 8);
        }
        asm volatile("cp.async.commit_group;" ::: "memory");
    };

    const int ra = (lane & 7) + ((lane >> 3) & 1) * 8;
    const int ka = lane >> 4;
    const int rb = (lane & 7) + ((lane >> 4) & 1) * 8;
    const int kb = (lane >> 3) & 1;

    load_stage(0);
    load_stage(1);

    for (int ch = 0; ch < PNCH; ch++) {
        // Drain correctly: on the last iteration only the current chunk's
        // group may be pending, so wait for ALL groups.
        if (ch + 1 < PNCH)
            asm volatile("cp.async.wait_group 1;" ::: "memory");
        else
            asm volatile("cp.async.wait_group 0;" ::: "memory");
        __syncthreads();

        if (ch + 2 < PNCH) load_stage(ch + 2);

        const int s = ch % P_STAGES;
        const uint32_t aw = sb + s * P_ST + (warpM * 32) * 128;
        const uint32_t bw = sb + s * P_ST + PX_ST + (warpN * 32) * 128;

#pragma unroll
        for (int ks = 0; ks < 4; ks++) {
            uint32_t af[2][4];
#pragma unroll
            for (int mi = 0; mi < 2; mi++) {
                uint32_t addr = aw + (mi * 16 + ra) * 128
                              + (((uint32_t)(ks * 2 + ka) ^ lane7) * 16);
                ldsm_x4(af[mi], addr);
            }
            uint32_t bf[4][2];
#pragma unroll
            for (int nj = 0; nj < 2; nj++) {
                uint32_t t[4];
                uint32_t addr = bw + (nj * 16 + rb) * 128
                              + (((uint32_t)(ks * 2 + kb) ^ lane7) * 16);
                ldsm_x4(t, addr);
                bf[2 * nj][0] = t[0]; bf[2 * nj][1] = t[1];
                bf[2 * nj + 1][0] = t[2]; bf[2 * nj + 1][1] = t[3];
            }
#pragma unroll
            for (int mi = 0; mi < 2; mi++)
#pragma unroll
                for (int ni = 0; ni < 4; ni++)
                    mma_f16_16816(acc[mi][ni], af[mi], bf[ni]);
        }
        __syncthreads();
    }

    // epilogue: select adapter slice, scale, write ext cols
#pragma unroll
    for (int mi = 0; mi < 2; mi++) {
        const int r0 = warpM * 32 + mi * 16 + gid;
        const int r1 = r0 + 8;
        const int aid0 = mapping[tBase + r0];
        const int aid1 = mapping[tBase + r1];
        const float s0 = (aid0 > 0) ? scaling[aid0 - 1] : 0.0f;
        const float s1 = (aid1 > 0) ? scaling[aid1 - 1] : 0.0f;
#pragma unroll
        for (int ni = 0; ni < 4; ni++) {
            const int col = warpN * 32 + ni * 8 + tig * 2;
            const bool sel0 = (aid0 > 0) && ((col >> 4) == aid0 - 1);
            const bool sel1 = (aid1 > 0) && ((col >> 4) == aid1 - 1);
            uint32_t v0 = sel0 ? pack_h2(acc[mi][ni][0] * s0, acc[mi][ni][1] * s0) : 0u;
            uint32_t v1 = sel1 ? pack_h2(acc[mi][ni][2] * s1, acc[mi][ni][3] * s1) : 0u;
            *(uint32_t*)(g_xh + (size_t)(tBase + r0) * KTOT + DIN + col) = v0;
            *(uint32_t*)(g_xh + (size_t)(tBase + r1) * KTOT + DIN + col) = v1;
        }
    }
}

// ---------------------------------------------------------------------------
// Main GEMM (best measured, unchanged): CTA 256x128, 16 warps (4Mx4N),
// warp tile 64x32, BK=128 (256B rows), 2-stage double buffer.
// ---------------------------------------------------------------------------
__global__ void __launch_bounds__(512, 1) gemm_h_kernel(
    const float* __restrict__ bias, float* __restrict__ out)
{
    extern __shared__ char smem[];
    const uint32_t sb = smem_u32(smem);
    const int tid  = threadIdx.x;
    const int wid  = tid >> 5;
    const int lane = tid & 31;
    const int gid  = lane >> 2;
    const int tig  = lane & 3;
    const int warpM = wid & 3;      // 0..3 -> 64 rows each
    const int warpN = wid >> 2;     // 0..3 -> 32 cols each
    const int mBase = blockIdx.y * BM;
    const int oBase = blockIdx.x * BN;
    const uint32_t lane7 = lane & 7;

    float acc[4][4][4];
#pragma unroll
    for (int mi = 0; mi < 4; mi++)
#pragma unroll
        for (int n = 0; n < 4; n++)
#pragma unroll
            for (int q = 0; q < 4; q++) acc[mi][n][q] = 0.0f;

    const int srow = tid >> 4;      // 0..31
    const int sseg = tid & 15;      // 0..15
    const uint32_t st_off = (uint32_t)(sseg >> 3) * 128
                          + (uint32_t)((sseg & 7) ^ (srow & 7)) * 16;

    auto load_stage = [&](int chunk, int slot) {
        const uint32_t abase = sb + slot * ST_BYTES;
        const uint32_t bbase = abase + A_ST;
        const size_t koff = (size_t)chunk * BKL + sseg * 8;
#pragma unroll
        for (int t = 0; t < 8; t++) {           // A: 256 rows
            int row = srow + t * 32;
            cp_async16(abase + row * 256 + st_off,
                       g_xh + (size_t)(mBase + row) * KTOT + koff);
        }
#pragma unroll
        for (int t = 0; t < 4; t++) {           // B: 128 rows
            int row = srow + t * 32;
            cp_async16(bbase + row * 256 + st_off,
                       g_wh + (size_t)(oBase + row) * KTOT + koff);
        }
        asm volatile("cp.async.commit_group;" ::: "memory");
    };

    load_stage(0, 0);

    const int ra = (lane & 7) + ((lane >> 3) & 1) * 8;
    const int ka = lane >> 4;
    const int rb = (lane & 7) + ((lane >> 4) & 1) * 8;
    const int kb = (lane >> 3) & 1;

    for (int i = 0; i < NCH; i++) {
        asm volatile("cp.async.wait_group 0;" ::: "memory");
        __syncthreads();

        if (i + 1 < NCH) load_stage(i + 1, (i + 1) & 1);

        const int slot = i & 1;
        const uint32_t aw = sb + slot * ST_BYTES + (warpM * 64) * 256;
        const uint32_t bw = sb + slot * ST_BYTES + A_ST + (warpN * 32) * 256;

#pragma unroll
        for (int ks = 0; ks < 8; ks++) {
            const uint32_t sa = (uint32_t)(ks * 2 + ka);
            const uint32_t sb2 = (uint32_t)(ks * 2 + kb);
            const uint32_t aoff = (sa >> 3) * 128 + (((sa & 7) ^ lane7) * 16);
            const uint32_t boff = (sb2 >> 3) * 128 + (((sb2 & 7) ^ lane7) * 16);

            uint32_t af[4][4];
#pragma unroll
            for (int mi = 0; mi < 4; mi++)
                ldsm_x4(af[mi], aw + (mi * 16 + ra) * 256 + aoff);

            uint32_t bf[4][2];
#pragma unroll
            for (int nj = 0; nj < 2; nj++) {
                uint32_t t[4];
                ldsm_x4(t, bw + (nj * 16 + rb) * 256 + boff);
                bf[2 * nj][0] = t[0]; bf[2 * nj][1] = t[1];
                bf[2 * nj + 1][0] = t[2]; bf[2 * nj + 1][1] = t[3];
            }
#pragma unroll
            for (int mi = 0; mi < 4; mi++)
#pragma unroll
                for (int n = 0; n < 4; n++)
                    mma_f16_16816(acc[mi][n], af[mi], bf[n]);
        }
    }

    // epilogue: bias + store
#pragma unroll
    for (int mi = 0; mi < 4; mi++) {
        const int row = mBase + warpM * 64 + mi * 16 + gid;
#pragma unroll
        for (int n = 0; n < 4; n++) {
            const int col = oBase + warpN * 32 + n * 8 + tig * 2;
            float2 b2 = *(const float2*)(bias + col);
            float2 o0, o1;
            o0.x = acc[mi][n][0] + b2.x;
            o0.y = acc[mi][n][1] + b2.y;
            o1.x = acc[mi][n][2] + b2.x;
            o1.y = acc[mi][n][3] + b2.y;
            *(float2*)(out + (size_t)row * DOUT + col) = o0;
            *(float2*)(out + (size_t)(row + 8) * DOUT + col) = o1;
        }
    }
}

// ---------------------------------------------------------------------------
// Inputs: x, lora_mapping, weight, bias, lora_a, lora_b, scaling
// ---------------------------------------------------------------------------
extern "C" void kernel_launch(void* const* d_in, const int* in_sizes, int n_in,
                              void* d_out, int out_size)
{
    const float* x       = (const float*)d_in[0];
    const int*   mapping = (const int*)  d_in[1];
    const float* weight  = (const float*)d_in[2];
    const float* bias    = (const float*)d_in[3];
    const float* lora_a  = (const float*)d_in[4];
    const float* lora_b  = (const float*)d_in[5];
    const float* scaling = (const float*)d_in[6];
    float*       out     = (float*)d_out;

    cudaFuncSetAttribute(gemm_h_kernel,
                         cudaFuncAttributeMaxDynamicSharedMemorySize, SMEM_BYTES);
    cudaFuncSetAttribute(u_xu_kernel,
                         cudaFuncAttributeMaxDynamicSharedMemorySize, P_SMEM_BYTES);

    conv_all_kernel<<<XCONV_BLOCKS + WCONV_BLOCKS, 256>>>(x, weight, lora_a, lora_b);
    u_xu_kernel<<<NXB, 256, P_SMEM_BYTES>>>(mapping, scaling);

    dim3 grid(DOUT / BN, NTOK / BM);
    gemm_h_kernel<<<grid, 512, SMEM_BYTES>>>(bias, out);
}